// round 1
// baseline (speedup 1.0000x reference)
#include <cuda_runtime.h>

#define NN 200000
#define NT 4

// Scratch: per-(type,dest) edge counts for the two edge sets.
__device__ int g_cnt1[NT * NN];
__device__ int g_cnt2[NT * NN];

__global__ void zero_counts_kernel() {
    int i = blockIdx.x * blockDim.x + threadIdx.x;
    if (i < NT * NN) { g_cnt1[i] = 0; g_cnt2[i] = 0; }
}

__global__ void count_kernel(const int* __restrict__ idx, const int* __restrict__ types,
                             int E, int shape, int which) {
    int e = blockIdx.x * blockDim.x + threadIdx.x;
    if (e >= E) return;
    int dest = idx[E * shape + e * shape];   // idx[1] row, first of each group
    int t = types[e];
    int* cnt = which ? g_cnt2 : g_cnt1;
    atomicAdd(&cnt[t * NN + dest], 1);
}

// out[n][o] = sum_d x[n][d] * Cw[o][d] + Cb[o]
// Block: 256 threads, 32 nodes. W^T staged in smem (padded stride 132), x tile in smem.
__global__ void dense_kernel(const float* __restrict__ x, const float* __restrict__ Cw,
                             const float* __restrict__ Cb, float* __restrict__ out,
                             int n_nodes) {
    extern __shared__ float sm[];
    float* Wt = sm;               // 128 * 132 (padded)
    float* xs = sm + 128 * 132;   // 32 * 128
    int tid = threadIdx.x;
    for (int i = tid; i < 128 * 128; i += 256) {
        int o = i >> 7, d = i & 127;
        Wt[d * 132 + o] = Cw[i];
    }
    int nb = blockIdx.x * 32;
    for (int i = tid; i < 32 * 32; i += 256) {
        int r = i >> 5, c = i & 31;
        int n = nb + r;
        float4 v = (n < n_nodes) ? ((const float4*)x)[(size_t)n * 32 + c]
                                 : make_float4(0.f, 0.f, 0.f, 0.f);
        ((float4*)(xs + r * 128))[c] = v;
    }
    __syncthreads();
    int warp = tid >> 5, lane = tid & 31;
    float acc[4][4] = {};
    const float* xw = xs + warp * 4 * 128;
    #pragma unroll 4
    for (int k = 0; k < 128; k++) {
        float w0 = Wt[k * 132 + lane];
        float w1 = Wt[k * 132 + lane + 32];
        float w2 = Wt[k * 132 + lane + 64];
        float w3 = Wt[k * 132 + lane + 96];
        #pragma unroll
        for (int q = 0; q < 4; q++) {
            float f = xw[q * 128 + k];
            acc[q][0] += f * w0; acc[q][1] += f * w1;
            acc[q][2] += f * w2; acc[q][3] += f * w3;
        }
    }
    float b0 = Cb[lane], b1 = Cb[lane + 32], b2 = Cb[lane + 64], b3 = Cb[lane + 96];
    #pragma unroll
    for (int q = 0; q < 4; q++) {
        int n = nb + warp * 4 + q;
        if (n < n_nodes) {
            float* o = out + (size_t)n * 128;
            o[lane]      = acc[q][0] + b0;
            o[lane + 32] = acc[q][1] + b1;
            o[lane + 64] = acc[q][2] + b2;
            o[lane + 96] = acc[q][3] + b3;
        }
    }
}

// Edge aggregation. Tile of 256 edges per block; for each of 4 types:
// stage full A[t] (K x 128) in smem, compact same-type edges, each warp processes
// 4 edges concurrently (A element reuse x4), scatter-adds norm-scaled outputs.
template <int SHAPE>
__global__ void edge_kernel(const float* __restrict__ x, const int* __restrict__ idx,
                            const int* __restrict__ types, const float* __restrict__ A,
                            int which, float* __restrict__ out, int E) {
    constexpr int K = SHAPE * 128;
    extern __shared__ float sm[];
    float* A_s   = sm;                         // K * 128
    float* feats = A_s + K * 128;              // 8 warps * 4 edges * K
    int*   s_src  = (int*)(feats + 8 * 4 * K); // 256 * SHAPE
    int*   s_dest = s_src + 256 * SHAPE;       // 256
    float* s_norm = (float*)(s_dest + 256);    // 256
    int*   s_type = (int*)(s_norm + 256);      // 256
    int*   s_list = s_type + 256;              // 256
    __shared__ int s_cnt;

    const int* cnt = which ? g_cnt2 : g_cnt1;
    int tid = threadIdx.x, warp = tid >> 5, lane = tid & 31;
    int numTiles = (E + 255) >> 8;

    for (int tile = blockIdx.x; tile < numTiles; tile += gridDim.x) {
        int e = tile * 256 + tid;
        if (e < E) {
            #pragma unroll
            for (int j = 0; j < SHAPE; j++) s_src[tid * SHAPE + j] = idx[e * SHAPE + j];
            int dest = idx[E * SHAPE + e * SHAPE];
            int t = types[e];
            s_dest[tid] = dest;
            s_type[tid] = t;
            s_norm[tid] = 1.0f / (float)cnt[t * NN + dest];
        } else {
            #pragma unroll
            for (int j = 0; j < SHAPE; j++) s_src[tid * SHAPE + j] = 0;
            s_dest[tid] = 0; s_type[tid] = -1; s_norm[tid] = 0.f;
        }

        for (int t = 0; t < NT; t++) {
            __syncthreads();          // meta ready (t=0) / prior pass done (t>0)
            if (tid == 0) s_cnt = 0;
            __syncthreads();
            if (s_type[tid] == t) { int p = atomicAdd(&s_cnt, 1); s_list[p] = tid; }
            // stage A[t] -> smem
            const float4* Ag = (const float4*)(A + (size_t)t * K * 128);
            float4* As4 = (float4*)A_s;
            for (int i = tid; i < K * 32; i += 256) As4[i] = Ag[i];
            __syncthreads();
            int m = s_cnt;

            for (int base = warp * 4; base < m; base += 32) {
                int eidx[4]; float nrm[4];
                #pragma unroll
                for (int q = 0; q < 4; q++) {
                    int p = base + q;
                    bool v = (p < m);
                    eidx[q] = s_list[v ? p : base];
                    nrm[q]  = v ? s_norm[eidx[q]] : 0.f;
                }
                // stage feats for the 4 edges (per-warp region)
                float* wf = feats + warp * 4 * K;
                #pragma unroll
                for (int q = 0; q < 4; q++) {
                    #pragma unroll
                    for (int j = 0; j < SHAPE; j++) {
                        int src = s_src[eidx[q] * SHAPE + j];
                        ((float4*)(wf + q * K + j * 128))[lane] =
                            ((const float4*)(x + (size_t)src * 128))[lane];
                    }
                }
                __syncwarp();
                float acc[4][4] = {};
                #pragma unroll 4
                for (int k = 0; k < K; k++) {
                    float a0 = A_s[k * 128 + lane];
                    float a1 = A_s[k * 128 + lane + 32];
                    float a2 = A_s[k * 128 + lane + 64];
                    float a3 = A_s[k * 128 + lane + 96];
                    #pragma unroll
                    for (int q = 0; q < 4; q++) {
                        float f = wf[q * K + k];
                        acc[q][0] += f * a0; acc[q][1] += f * a1;
                        acc[q][2] += f * a2; acc[q][3] += f * a3;
                    }
                }
                #pragma unroll
                for (int q = 0; q < 4; q++) {
                    float* o = out + (size_t)s_dest[eidx[q]] * 128;
                    float nv = nrm[q];
                    atomicAdd(o + lane,      acc[q][0] * nv);
                    atomicAdd(o + lane + 32, acc[q][1] * nv);
                    atomicAdd(o + lane + 64, acc[q][2] * nv);
                    atomicAdd(o + lane + 96, acc[q][3] * nv);
                }
                __syncwarp();   // before reusing wf
            }
        }
        __syncthreads();        // before next tile overwrites meta
    }
}

extern "C" void kernel_launch(void* const* d_in, const int* in_sizes, int n_in,
                              void* d_out, int out_size) {
    const float* x     = (const float*)d_in[0];
    const int*   idx1  = (const int*)d_in[1];
    const int*   type1 = (const int*)d_in[2];
    const int*   idx2  = (const int*)d_in[3];
    const int*   type2 = (const int*)d_in[4];
    const float* Cw    = (const float*)d_in[5];
    const float* Cb    = (const float*)d_in[6];
    const float* A1    = (const float*)d_in[7];
    const float* A2    = (const float*)d_in[8];
    float* out = (float*)d_out;

    int E1v = in_sizes[2];             // type1 count
    int E2v = in_sizes[4];             // type2 count
    int n_nodes = in_sizes[0] / 128;

    int smem_dense = (128 * 132 + 32 * 128) * 4;
    int smem_e1 = (128 * 128 + 8 * 4 * 128) * 4 + (256 * 1 + 256 * 4) * 4;
    int smem_e2 = (256 * 128 + 8 * 4 * 256) * 4 + (256 * 2 + 256 * 4) * 4;

    cudaFuncSetAttribute(dense_kernel, cudaFuncAttributeMaxDynamicSharedMemorySize, smem_dense);
    cudaFuncSetAttribute(edge_kernel<1>, cudaFuncAttributeMaxDynamicSharedMemorySize, smem_e1);
    cudaFuncSetAttribute(edge_kernel<2>, cudaFuncAttributeMaxDynamicSharedMemorySize, smem_e2);

    zero_counts_kernel<<<(NT * NN + 255) / 256, 256>>>();
    count_kernel<<<(E1v + 255) / 256, 256>>>(idx1, type1, E1v, 1, 0);
    count_kernel<<<(E2v + 255) / 256, 256>>>(idx2, type2, E2v, 2, 1);
    dense_kernel<<<(n_nodes + 31) / 32, 256, smem_dense>>>(x, Cw, Cb, out, n_nodes);
    edge_kernel<1><<<(E1v + 255) / 256, 256, smem_e1>>>(x, idx1, type1, A1, 0, out, E1v);
    edge_kernel<2><<<(E2v + 255) / 256, 256, smem_e2>>>(x, idx2, type2, A2, 1, out, E2v);
}